// round 15
// baseline (speedup 1.0000x reference)
#include <cuda_runtime.h>
#include <math_constants.h>
#include <cstdint>

#define BATCH 2
#define SEQ 2048
#define DMODEL 1024
#define NHEADS 16
#define HDIM 64
#define ROWS (BATCH*SEQ)   // 4096

// Scratch (allocation-free rule: __device__ globals).
__device__ float    g_q[(size_t)ROWS * DMODEL];
__device__ float    g_k[(size_t)ROWS * DMODEL];
__device__ float    g_v[(size_t)ROWS * DMODEL];
__device__ float    g_att[(size_t)ROWS * DMODEL];
__device__ uint32_t g_xc[(size_t)ROWS * DMODEL];          // tf32 bits of x
__device__ uint32_t g_wc[(size_t)4 * DMODEL * DMODEL];    // tf32 bits of Wq,Wk,Wv,Wo

// Single dynamic smem symbol shared by all kernels.
extern __shared__ char dynsm[];

// ===========================================================================
// Helpers
// ===========================================================================
__device__ __forceinline__ uint32_t smem_u32(const void* p) {
    uint32_t a;
    asm("{ .reg .u64 t; cvta.to.shared.u64 t, %1; cvt.u32.u64 %0, t; }"
        : "=r"(a) : "l"(p));
    return a;
}
__device__ __forceinline__ void cp_async16(uint32_t dst, const void* src) {
    asm volatile("cp.async.cg.shared.global [%0], [%1], 16;"
                 :: "r"(dst), "l"(src));
}
#define CP_COMMIT() asm volatile("cp.async.commit_group;" ::: "memory")
#define CP_WAIT(n)  asm volatile("cp.async.wait_group %0;" :: "n"(n) : "memory")

__device__ __forceinline__ uint32_t f2tf32(float f) {
    uint32_t r;
    asm("cvt.rna.tf32.f32 %0, %1;" : "=r"(r) : "f"(f));
    return r;
}
__device__ __forceinline__ void mma_tf32(float c[4],
                                         const uint32_t a[4],
                                         const uint32_t b[2]) {
    asm volatile(
        "mma.sync.aligned.m16n8k8.row.col.f32.tf32.tf32.f32 "
        "{%0,%1,%2,%3}, {%4,%5,%6,%7}, {%8,%9}, {%0,%1,%2,%3};"
        : "+f"(c[0]), "+f"(c[1]), "+f"(c[2]), "+f"(c[3])
        : "r"(a[0]), "r"(a[1]), "r"(a[2]), "r"(a[3]), "r"(b[0]), "r"(b[1]));
}
__device__ __forceinline__ void mma_tf32_b2(float c[4],
                                            const uint32_t a[4],
                                            uint32_t b0, uint32_t b1) {
    asm volatile(
        "mma.sync.aligned.m16n8k8.row.col.f32.tf32.tf32.f32 "
        "{%0,%1,%2,%3}, {%4,%5,%6,%7}, {%8,%9}, {%0,%1,%2,%3};"
        : "+f"(c[0]), "+f"(c[1]), "+f"(c[2]), "+f"(c[3])
        : "r"(a[0]), "r"(a[1]), "r"(a[2]), "r"(a[3]), "r"(b0), "r"(b1));
}
// ldmatrix.x4: four 8x8 b16 tiles == the 16x8(x2) tf32 NT fragment pattern.
__device__ __forceinline__ void ldsm_x4(uint32_t& r0, uint32_t& r1,
                                        uint32_t& r2, uint32_t& r3,
                                        uint32_t addr) {
    asm volatile(
        "ldmatrix.sync.aligned.m8n8.x4.shared.b16 {%0,%1,%2,%3}, [%4];"
        : "=r"(r0), "=r"(r1), "=r"(r2), "=r"(r3) : "r"(addr));
}

// ===========================================================================
// Pre-pass: round x + all weights to tf32 bits once.
// ===========================================================================
__global__ __launch_bounds__(256) void convert_tf32_kernel(
    const float* __restrict__ x,  const float* __restrict__ wq,
    const float* __restrict__ wk, const float* __restrict__ wv,
    const float* __restrict__ wo)
{
    const int idx = blockIdx.x * 256 + threadIdx.x;   // float4 index
    const float* src;
    uint32_t*    dst;
    if (idx < (1 << 20)) {
        src = x + (size_t)idx * 4;
        dst = g_xc + (size_t)idx * 4;
    } else {
        const int j   = idx - (1 << 20);
        const int w   = j >> 18;                      // 256K float4 per W
        const int off = j & ((1 << 18) - 1);
        const float* ws = (w == 0) ? wq : (w == 1) ? wk : (w == 2) ? wv : wo;
        src = ws + (size_t)off * 4;
        dst = g_wc + (size_t)w * DMODEL * DMODEL + (size_t)off * 4;
    }
    const float4 v = *reinterpret_cast<const float4*>(src);
    *reinterpret_cast<uint4*>(dst) =
        make_uint4(f2tf32(v.x), f2tf32(v.y), f2tf32(v.z), f2tf32(v.w));
}

// ===========================================================================
// tf32 mma.sync SGEMM_NT on pre-rounded bits: C = A * Bw^T, 128x128 block
// tile, 4 warps (2x2), warp tile 64x64, 128 threads. BK=16, 4-stage cp.async
// ring with ONE __syncthreads per chunk; fragments via ldmatrix.x4.
// Epilogue modes: 0 = plain store, 1 = tf32-round (V),
//                 2 = RoPE + 1/8 scale + round (Q), 3 = RoPE + round (K).
// ===========================================================================
constexpr int G_BK     = 16;
constexpr int G_NCHUNK = DMODEL / G_BK;    // 64
constexpr int G_SSTR   = 20;
constexpr int G_NST    = 4;
constexpr int G_STW    = 128 * G_SSTR;     // words per stage per matrix (2560)
constexpr int G_SMEM   = 2 * G_NST * G_STW * 4;   // 81920 bytes

__device__ __forceinline__ void gemm_tile_w64(
    const uint32_t* __restrict__ A, const uint32_t* __restrict__ Bw,
    float* __restrict__ C, int crow0, int ccol0, int mode,
    const float* __restrict__ cosp, const float* __restrict__ sinp)
{
    uint32_t* Asm = reinterpret_cast<uint32_t*>(dynsm);
    uint32_t* Bsm = Asm + G_NST * G_STW;

    const int tid  = threadIdx.x;        // 0..127
    const int wid  = tid >> 5;
    const int lane = tid & 31;
    const int wm   = wid & 1;            // 64-row band
    const int wn   = wid >> 1;           // 64-col band
    const int gid  = lane >> 2;          // 0..7
    const int tig  = lane & 3;           // 0..3
    // ldmatrix per-lane addressing
    const int quad   = lane >> 3;
    const int i8     = lane & 7;
    const int rowoff = ((quad & 1) << 3) + i8;
    const int coloff = (quad >> 1) << 2;

    uint32_t aB[G_NST], bB[G_NST];
    #pragma unroll
    for (int s = 0; s < G_NST; s++) {
        aB[s] = smem_u32(&Asm[s * G_STW + (wm * 64 + rowoff) * G_SSTR + coloff]);
        bB[s] = smem_u32(&Bsm[s * G_STW + (wn * 64 + rowoff) * G_SSTR + coloff]);
    }

    const uint32_t* gA = A  + (size_t)crow0 * DMODEL;
    const uint32_t* gB = Bw + (size_t)ccol0 * DMODEL;

    auto load_chunk = [&](int c) {
        const int st = c & 3;
        #pragma unroll
        for (int i = 0; i < 4; i++) {
            const int idx = i * 128 + tid;     // [0,512) float4 slots
            const int row = idx >> 2, c4 = idx & 3;
            const size_t g = (size_t)row * DMODEL + c * G_BK + c4 * 4;
            cp_async16(smem_u32(&Asm[st * G_STW + row * G_SSTR + c4 * 4]), gA + g);
            cp_async16(smem_u32(&Bsm[st * G_STW + row * G_SSTR + c4 * 4]), gB + g);
        }
        CP_COMMIT();
    };

    float acc[4][8][4];
    #pragma unroll
    for (int mi = 0; mi < 4; mi++)
        #pragma unroll
        for (int ni = 0; ni < 8; ni++)
            #pragma unroll
            for (int r = 0; r < 4; r++) acc[mi][ni][r] = 0.f;

    uint32_t afA[4][4], bfA[8][2], afB[4][4], bfB[8][2];

    auto load_frags = [&](uint32_t af[4][4], uint32_t bf[8][2],
                          int st, int kb) {
        const uint32_t ab = aB[st] + kb * 4;
        const uint32_t bb = bB[st] + kb * 4;
        #pragma unroll
        for (int mi = 0; mi < 4; mi++)
            ldsm_x4(af[mi][0], af[mi][1], af[mi][2], af[mi][3],
                    ab + mi * (16 * G_SSTR * 4));
        #pragma unroll
        for (int p = 0; p < 4; p++) {
            uint32_t r0, r1, r2, r3;
            ldsm_x4(r0, r1, r2, r3, bb + p * (16 * G_SSTR * 4));
            bf[2 * p][0] = r0;  bf[2 * p + 1][0] = r1;
            bf[2 * p][1] = r2;  bf[2 * p + 1][1] = r3;
        }
    };
    auto mma_all = [&](const uint32_t af[4][4], const uint32_t bf[8][2]) {
        #pragma unroll
        for (int mi = 0; mi < 4; mi++)
            #pragma unroll
            for (int ni = 0; ni < 8; ni++)
                mma_tf32(acc[mi][ni], af[mi], bf[ni]);
    };

    // Prologue: 3 stages in flight.
    load_chunk(0);
    load_chunk(1);
    load_chunk(2);

    for (int c = 0; c < G_NCHUNK; c++) {
        CP_WAIT(2);            // chunk c landed (pending <= {c+1, c+2})
        __syncthreads();       // c's data visible; stage (c-1)&3 reads drained
        if (c + 3 < G_NCHUNK) load_chunk(c + 3);   // refill stage (c-1)&3
        else                  CP_COMMIT();         // uniform group accounting
        const int st = c & 3;
        load_frags(afA, bfA, st, 0);
        load_frags(afB, bfB, st, 8);
        mma_all(afA, bfA);
        mma_all(afB, bfB);
    }

    // ---- RoPE epilogue (modes 2/3): rotate in registers, then tf32-round.
    if (mode >= 2) {
        const float qs = (mode == 2) ? 0.125f : 1.0f;
        #pragma unroll
        for (int mi = 0; mi < 4; mi++) {
            #pragma unroll
            for (int rh = 0; rh < 2; rh++) {
                const int row = crow0 + wm * 64 + mi * 16 + gid + rh * 8;
                const int s   = row & (SEQ - 1);
                const float* cr = cosp + s * HDIM;
                const float* sr = sinp + s * HDIM;
                #pragma unroll
                for (int ni = 0; ni < 4; ni++) {
                    const int d = ni * 8 + 2 * tig;      // < 32
                    const float2 c1 = *reinterpret_cast<const float2*>(cr + d);
                    const float2 s1 = *reinterpret_cast<const float2*>(sr + d);
                    const float2 c2 = *reinterpret_cast<const float2*>(cr + d + 32);
                    const float2 s2 = *reinterpret_cast<const float2*>(sr + d + 32);
                    const float v1a = acc[mi][ni    ][rh * 2 + 0];
                    const float v1b = acc[mi][ni    ][rh * 2 + 1];
                    const float v2a = acc[mi][ni + 4][rh * 2 + 0];
                    const float v2b = acc[mi][ni + 4][rh * 2 + 1];
                    acc[mi][ni    ][rh * 2 + 0] =
                        __uint_as_float(f2tf32((v1a * c1.x - v2a * s1.x) * qs));
                    acc[mi][ni    ][rh * 2 + 1] =
                        __uint_as_float(f2tf32((v1b * c1.y - v2b * s1.y) * qs));
                    acc[mi][ni + 4][rh * 2 + 0] =
                        __uint_as_float(f2tf32((v2a * c2.x + v1a * s2.x) * qs));
                    acc[mi][ni + 4][rh * 2 + 1] =
                        __uint_as_float(f2tf32((v2b * c2.y + v1b * s2.y) * qs));
                }
            }
        }
    }

    const bool rnd = (mode == 1);
    #pragma unroll
    for (int mi = 0; mi < 4; mi++) {
        const int row = crow0 + wm * 64 + mi * 16 + gid;
        #pragma unroll
        for (int ni = 0; ni < 8; ni++) {
            const int col = ccol0 + wn * 64 + ni * 8 + tig * 2;
            float v0 = acc[mi][ni][0], v1 = acc[mi][ni][1];
            float v2 = acc[mi][ni][2], v3 = acc[mi][ni][3];
            if (rnd) {
                v0 = __uint_as_float(f2tf32(v0));
                v1 = __uint_as_float(f2tf32(v1));
                v2 = __uint_as_float(f2tf32(v2));
                v3 = __uint_as_float(f2tf32(v3));
            }
            *reinterpret_cast<float2*>(&C[(size_t)row * DMODEL + col]) =
                make_float2(v0, v1);
            *reinterpret_cast<float2*>(&C[(size_t)(row + 8) * DMODEL + col]) =
                make_float2(v2, v3);
        }
    }
}

// Fused QKV (+RoPE): grid.x = 24 (3 weights x 8 col tiles), grid.y = 32
__global__ __launch_bounds__(128) void qkv_gemm_mma(
    const float* __restrict__ cosp, const float* __restrict__ sinp)
{
    const int g  = blockIdx.x >> 3;
    const int bx = blockIdx.x & 7;
    float* Cp; int mode;
    if      (g == 0) { Cp = g_q; mode = 2; }   // Q: rope + 1/8 + round
    else if (g == 1) { Cp = g_k; mode = 3; }   // K: rope + round
    else             { Cp = g_v; mode = 1; }   // V: round
    gemm_tile_w64(g_xc, g_wc + (size_t)g * DMODEL * DMODEL, Cp,
                  blockIdx.y * 128, bx * 128, mode, cosp, sinp);
}

__global__ __launch_bounds__(128) void out_gemm_mma(float* __restrict__ out)
{
    gemm_tile_w64(reinterpret_cast<const uint32_t*>(g_att),
                  g_wc + (size_t)3 * DMODEL * DMODEL, out,
                  blockIdx.y * 128, blockIdx.x * 128, 0, nullptr, nullptr);
}

// ===========================================================================
// Tensor-core causal flash attention (tf32 mma.sync), operands pre-rounded.
// Block: 256 threads (8 warps); two paired 128-row q-tiles (qt, 15-qt).
// K/V 64x64 tiles double-buffered via cp.async. UNIFORM control flow:
// every warp processes every tile (masked tiles are exact no-ops thanks to
// m-init = -1e30 and -inf masking) -> ldmatrix is legal for Q/K/P.
// V stays scalar LDS (no .trans path for 32-bit data).
// ===========================================================================
#define AT_SK 68
#define AT_SV 72
#define AT_KFLOATS (64*AT_SK)               // 4352
#define AT_STAGE   (AT_KFLOATS + 64*AT_SV)  // 8960 floats per stage
#define AT_PS      (2*AT_STAGE)             // P/Q staging offset
#define AT_SMEM_BYTES ((AT_PS + 128*AT_SK) * 4)   // 106496

__global__ __launch_bounds__(256, 2) void attn_mma_kernel()
{
    float* sm = reinterpret_cast<float*>(dynsm);
    const int tid = threadIdx.x, wid = tid >> 5, lane = tid & 31;
    const int gid = lane >> 2, tig = lane & 3;
    const int quad   = lane >> 3;
    const int i8     = lane & 7;
    const int rowoff = ((quad & 1) << 3) + i8;
    const int coloff = (quad >> 1) << 2;
    const int bh = blockIdx.y, b = bh >> 4, h = bh & 15;
    const float* Qg = g_q + (size_t)b * SEQ * DMODEL + h * HDIM;
    const float* Kg = g_k + (size_t)b * SEQ * DMODEL + h * HDIM;
    const float* Vg = g_v + (size_t)b * SEQ * DMODEL + h * HDIM;
    float*       Og = g_att + (size_t)b * SEQ * DMODEL + h * HDIM;

    const uint32_t smBase   = smem_u32(sm);
    const uint32_t kFragOff = (rowoff * AT_SK + coloff) * 4;
    const uint32_t psBase   = smBase + AT_PS * 4;

    for (int half = 0; half < 2; half++) {
        const int qt    = half ? (15 - (int)blockIdx.x) : (int)blockIdx.x;
        const int qrow0 = qt * 128;
        const int m0    = wid * 16;
        const int r0    = qrow0 + m0;

        __syncthreads();                       // Ps free from previous half
        for (int i = tid; i < 2048; i += 256) {
            const int row = i >> 4, c4 = (i & 15) * 4;
            *reinterpret_cast<float4*>(&sm[AT_PS + row * AT_SK + c4]) =
                *reinterpret_cast<const float4*>(
                    &Qg[(size_t)(qrow0 + row) * DMODEL + c4]);
        }
        __syncthreads();
        uint32_t qf[8][4];
        {
            const uint32_t qb = psBase + ((m0 + rowoff) * AT_SK + coloff) * 4;
            #pragma unroll
            for (int kb = 0; kb < 8; kb++)
                ldsm_x4(qf[kb][0], qf[kb][1], qf[kb][2], qf[kb][3],
                        qb + kb * 32);
        }
        __syncthreads();

        float oacc[8][4];
        #pragma unroll
        for (int n = 0; n < 8; n++)
            #pragma unroll
            for (int r = 0; r < 4; r++) oacc[n][r] = 0.f;
        float mr0 = -1e30f, mr1 = -1e30f;      // finite: masked tiles = no-ops
        float lr0 = 0.f, lr1 = 0.f;
        const int ktmax = 2 * qt + 1;

        auto load_kv = [&](int kt, int st) {
            const float* Kp = Kg + (size_t)(kt * 64) * DMODEL;
            const float* Vp = Vg + (size_t)(kt * 64) * DMODEL;
            const uint32_t kd = smBase + (st * AT_STAGE) * 4;
            const uint32_t vd = kd + AT_KFLOATS * 4;
            #pragma unroll
            for (int i = 0; i < 4; i++) {
                const int idx = i * 256 + tid;
                const int row = idx >> 4, c4 = (idx & 15) * 4;
                const size_t g = (size_t)row * DMODEL + c4;
                cp_async16(kd + (row * AT_SK + c4) * 4, Kp + g);
                cp_async16(vd + (row * AT_SV + c4) * 4, Vp + g);
            }
            CP_COMMIT();
        };

        load_kv(0, 0);
        for (int kt = 0; kt <= ktmax; kt++) {
            const int st = kt & 1;
            const int k0 = kt * 64;
            if (kt < ktmax) { load_kv(kt + 1, st ^ 1); CP_WAIT(1); }
            else            { CP_WAIT(0); }
            __syncthreads();

            const uint32_t stageB = smBase + (st * AT_STAGE) * 4;
            const uint32_t* Vsm = reinterpret_cast<const uint32_t*>(
                &sm[st * AT_STAGE]) + AT_KFLOATS;

            float sacc[8][4];
            #pragma unroll
            for (int n = 0; n < 8; n++)
                #pragma unroll
                for (int r = 0; r < 4; r++) sacc[n][r] = 0.f;

            // QK^T: K fragments for 2 n-blocks per ldmatrix.x4 (uniform code)
            #pragma unroll
            for (int kb = 0; kb < 8; kb++) {
                const uint32_t kbb = stageB + kFragOff + kb * 32;
                #pragma unroll
                for (int p = 0; p < 4; p++) {
                    uint32_t r0v, r1v, r2v, r3v;
                    ldsm_x4(r0v, r1v, r2v, r3v, kbb + p * (16 * AT_SK * 4));
                    mma_tf32_b2(sacc[2 * p    ], qf[kb], r0v, r2v);
                    mma_tf32_b2(sacc[2 * p + 1], qf[kb], r1v, r3v);
                }
            }
            if (k0 + 63 > r0) {                // causal mask (warp-uniform)
                const int row0 = r0 + gid, row1 = row0 + 8;
                #pragma unroll
                for (int n = 0; n < 8; n++) {
                    const int c = k0 + n * 8 + 2 * tig;
                    if (c     > row0) sacc[n][0] = -CUDART_INF_F;
                    if (c + 1 > row0) sacc[n][1] = -CUDART_INF_F;
                    if (c     > row1) sacc[n][2] = -CUDART_INF_F;
                    if (c + 1 > row1) sacc[n][3] = -CUDART_INF_F;
                }
            }
            float cm0 = -CUDART_INF_F, cm1 = -CUDART_INF_F;
            #pragma unroll
            for (int n = 0; n < 8; n++) {
                cm0 = fmaxf(cm0, fmaxf(sacc[n][0], sacc[n][1]));
                cm1 = fmaxf(cm1, fmaxf(sacc[n][2], sacc[n][3]));
            }
            cm0 = fmaxf(cm0, __shfl_xor_sync(0xffffffffu, cm0, 1));
            cm0 = fmaxf(cm0, __shfl_xor_sync(0xffffffffu, cm0, 2));
            cm1 = fmaxf(cm1, __shfl_xor_sync(0xffffffffu, cm1, 1));
            cm1 = fmaxf(cm1, __shfl_xor_sync(0xffffffffu, cm1, 2));
            const float mn0 = fmaxf(mr0, cm0), mn1 = fmaxf(mr1, cm1);
            const float co0 = __expf(mr0 - mn0), co1 = __expf(mr1 - mn1);
            float ps0 = 0.f, ps1 = 0.f;
            uint32_t* Pw = reinterpret_cast<uint32_t*>(&sm[AT_PS + m0 * AT_SK]);
            #pragma unroll
            for (int n = 0; n < 8; n++) {
                const float p00 = __expf(sacc[n][0] - mn0);
                const float p01 = __expf(sacc[n][1] - mn0);
                const float p10 = __expf(sacc[n][2] - mn1);
                const float p11 = __expf(sacc[n][3] - mn1);
                ps0 += p00 + p01; ps1 += p10 + p11;
                *reinterpret_cast<uint2*>(
                    &Pw[gid * AT_SK + n * 8 + 2 * tig]) =
                    make_uint2(f2tf32(p00), f2tf32(p01));
                *reinterpret_cast<uint2*>(
                    &Pw[(gid + 8) * AT_SK + n * 8 + 2 * tig]) =
                    make_uint2(f2tf32(p10), f2tf32(p11));
                oacc[n][0] *= co0; oacc[n][1] *= co0;
                oacc[n][2] *= co1; oacc[n][3] *= co1;
            }
            ps0 += __shfl_xor_sync(0xffffffffu, ps0, 1);
            ps0 += __shfl_xor_sync(0xffffffffu, ps0, 2);
            ps1 += __shfl_xor_sync(0xffffffffu, ps1, 1);
            ps1 += __shfl_xor_sync(0xffffffffu, ps1, 2);
            lr0 = lr0 * co0 + ps0;  lr1 = lr1 * co1 + ps1;
            mr0 = mn0;  mr1 = mn1;
            __syncwarp();
            const uint32_t pwb = psBase + ((m0 + rowoff) * AT_SK + coloff) * 4;
            #pragma unroll
            for (int kb = 0; kb < 8; kb++) {
                uint32_t pf[4];
                ldsm_x4(pf[0], pf[1], pf[2], pf[3], pwb + kb * 32);
                #pragma unroll
                for (int n = 0; n < 8; n++) {
                    const uint32_t* vr =
                        &Vsm[(kb * 8 + tig) * AT_SV + n * 8 + gid];
                    mma_tf32_b2(oacc[n], pf, vr[0], vr[4 * AT_SV]);
                }
            }
            __syncthreads();
        }

        // Write O tf32-rounded so out_gemm consumes bits directly.
        const float i0 = 1.f / lr0, i1 = 1.f / lr1;
        #pragma unroll
        for (int n = 0; n < 8; n++) {
            const int col = n * 8 + 2 * tig;
            *reinterpret_cast<float2*>(
                &Og[(size_t)(r0 + gid) * DMODEL + col]) =
                make_float2(__uint_as_float(f2tf32(oacc[n][0] * i0)),
                            __uint_as_float(f2tf32(oacc[n][1] * i0)));
            *reinterpret_cast<float2*>(
                &Og[(size_t)(r0 + gid + 8) * DMODEL + col]) =
                make_float2(__uint_as_float(f2tf32(oacc[n][2] * i1)),
                            __uint_as_float(f2tf32(oacc[n][3] * i1)));
        }
    }
}

// ---------------------------------------------------------------------------
extern "C" void kernel_launch(void* const* d_in, const int* in_sizes, int n_in,
                              void* d_out, int out_size)
{
    const float* x    = (const float*)d_in[0];
    const float* cosp = (const float*)d_in[1];
    const float* sinp = (const float*)d_in[2];
    const float* Wq   = (const float*)d_in[3];
    const float* Wk   = (const float*)d_in[4];
    const float* Wv   = (const float*)d_in[5];
    const float* Wo   = (const float*)d_in[6];
    float* out = (float*)d_out;

    cudaFuncSetAttribute(attn_mma_kernel,
        cudaFuncAttributeMaxDynamicSharedMemorySize, AT_SMEM_BYTES);
    cudaFuncSetAttribute(qkv_gemm_mma,
        cudaFuncAttributeMaxDynamicSharedMemorySize, G_SMEM);
    cudaFuncSetAttribute(out_gemm_mma,
        cudaFuncAttributeMaxDynamicSharedMemorySize, G_SMEM);

    convert_tf32_kernel<<<8192, 256>>>(x, Wq, Wk, Wv, Wo);
    qkv_gemm_mma<<<dim3(24, 32), 128, G_SMEM>>>(cosp, sinp);
    attn_mma_kernel<<<dim3(8, 32), 256, AT_SMEM_BYTES>>>();
    out_gemm_mma<<<dim3(8, 32), 128, G_SMEM>>>(out);
}